// round 2
// baseline (speedup 1.0000x reference)
#include <cuda_runtime.h>
#include <cstddef>
#include <cstdint>

#define VOCAB 32000
#define E 512
#define H 1024
#define G 4096            // 4*H
#define B 64
#define T 512
#define M1 (B*T)          // 32768
#define NCTA 128
#define LN_EPS 1e-5f

// ---------------- static device scratch (no cudaMalloc allowed) ----------------
__device__ float g_emb[(size_t)M1 * E];        // 64 MB  gathered embeddings
__device__ float g_xg[(size_t)M1 * G];         // 512 MB xg = emb@W_i + (b_i+b_h), permuted cols
__device__ float g_Wip[(size_t)E * G];         // 8 MB   permuted W_i
__device__ float g_Whp[(size_t)H * G];         // 16 MB  permuted W_h
__device__ float g_bp[G];                      // fused permuted bias
__device__ float g_h[B * H];                   // recurrent hidden state
__device__ float g_part[2][B][NCTA];           // LN partials (sum, sumsq)
__device__ unsigned g_arrive;                  // grid-barrier arrivals (monotonic)
__device__ unsigned g_release;                 // grid-barrier release generation (monotonic)

// ---------------- prep: permute weights, fuse biases ----------------
// permuted col p = 4*j + gate  <-  original col = gate*H + j   (gate order i,f,o,g)
__global__ void prep_kernel(const float* __restrict__ Wi, const float* __restrict__ bi,
                            const float* __restrict__ Wh, const float* __restrict__ bh) {
    int stride = gridDim.x * blockDim.x;
    for (int i = blockIdx.x * blockDim.x + threadIdx.x; i < H * G; i += stride) {
        int k = i >> 12;          // row
        int p = i & 4095;         // permuted col
        int j = p >> 2;
        int gi = p & 3;
        int oc = gi * H + j;      // original col
        g_Whp[i] = Wh[(size_t)k * G + oc];
        if (k < E) g_Wip[i] = Wi[(size_t)k * G + oc];
        if (k == 0) g_bp[p] = bi[oc] + bh[oc];
    }
}

// ---------------- embedding gather (padding_idx = 0) ----------------
__global__ void embed_kernel(const int* __restrict__ src, const float* __restrict__ tab) {
    int total = M1 * (E / 4);
    int stride = gridDim.x * blockDim.x;
    for (int i = blockIdx.x * blockDim.x + threadIdx.x; i < total; i += stride) {
        int m = i >> 7;           // token row (b*T + t)
        int e4 = i & 127;         // float4 index within row
        int row = src[m];
        float4 v;
        if (row == 0) { v.x = v.y = v.z = v.w = 0.f; }
        else v = *(const float4*)&tab[(size_t)row * E + e4 * 4];
        *(float4*)&g_emb[(size_t)m * E + e4 * 4] = v;
    }
}

// ---------------- phase-1 GEMM: xg = emb @ Wip + bp ----------------
// C[32768 x 4096], K=512. BM=128, BN=64, BK=16, 256 threads, 8x4 per thread.
#define FMA4(ac, s, bv) { (ac).x += (s)*(bv).x; (ac).y += (s)*(bv).y; (ac).z += (s)*(bv).z; (ac).w += (s)*(bv).w; }

__global__ void __launch_bounds__(256) xg_gemm() {
    __shared__ float a_s[16][132];   // [k][m], padded
    __shared__ float b_s[16][64];    // [k][n]
    int tid = threadIdx.x;
    int n0 = blockIdx.x * 64;
    int m0 = blockIdx.y * 128;
    int tx = tid & 15;               // -> 4 cols
    int ty = tid >> 4;               // -> 8 rows
    float4 acc[8];
#pragma unroll
    for (int r = 0; r < 8; r++) { acc[r].x = acc[r].y = acc[r].z = acc[r].w = 0.f; }

    int lk = tid & 3, lm = tid >> 2;     // A loader
    int bk = tid >> 4, bn = tid & 15;    // B loader

    for (int kt = 0; kt < E; kt += 16) {
#pragma unroll
        for (int h2 = 0; h2 < 2; h2++) {
            int m = lm + h2 * 64;
            float4 v = *(const float4*)&g_emb[(size_t)(m0 + m) * E + kt + lk * 4];
            a_s[lk * 4 + 0][m] = v.x;
            a_s[lk * 4 + 1][m] = v.y;
            a_s[lk * 4 + 2][m] = v.z;
            a_s[lk * 4 + 3][m] = v.w;
        }
        *(float4*)&b_s[bk][bn * 4] = *(const float4*)&g_Wip[(size_t)(kt + bk) * G + n0 + bn * 4];
        __syncthreads();
#pragma unroll
        for (int k = 0; k < 16; k++) {
            float4 a0 = *(const float4*)&a_s[k][ty * 8];
            float4 a1 = *(const float4*)&a_s[k][ty * 8 + 4];
            float4 bv = *(const float4*)&b_s[k][tx * 4];
            FMA4(acc[0], a0.x, bv); FMA4(acc[1], a0.y, bv);
            FMA4(acc[2], a0.z, bv); FMA4(acc[3], a0.w, bv);
            FMA4(acc[4], a1.x, bv); FMA4(acc[5], a1.y, bv);
            FMA4(acc[6], a1.z, bv); FMA4(acc[7], a1.w, bv);
        }
        __syncthreads();
    }
    float4 bias = *(const float4*)&g_bp[n0 + tx * 4];
#pragma unroll
    for (int r = 0; r < 8; r++) {
        float4 o;
        o.x = acc[r].x + bias.x; o.y = acc[r].y + bias.y;
        o.z = acc[r].z + bias.z; o.w = acc[r].w + bias.w;
        *(float4*)&g_xg[(size_t)(m0 + ty * 8 + r) * G + n0 + tx * 4] = o;
    }
}

// ---------------- grid barrier (monotonic generation; graph-replay-safe) ----------------
__device__ __forceinline__ void gridbar(unsigned target) {
    __syncthreads();
    if (threadIdx.x == 0) {
        __threadfence();
        unsigned prev = atomicAdd(&g_arrive, 1u);
        if (prev + 1u == target * NCTA) {
            atomicExch(&g_release, target);
        } else {
            while (atomicAdd(&g_release, 0u) < target) { __nanosleep(64); }
        }
        __threadfence();
    }
    __syncthreads();
}

// ---------------- persistent recurrent kernel ----------------
// 128 CTAs x 128 threads. CTA owns permuted cols [32*cta, 32*cta+32) = units [8*cta, 8*cta+8).
// W_h slice (1024x32, 128 KB) resident in SMEM for all 512 steps.
#define KC 128
#define AS_STRIDE 132
#define LSTM_SMEM_FLOATS (H * 32 + 64 * AS_STRIDE + 128)
#define LSTM_SMEM_BYTES (LSTM_SMEM_FLOATS * 4)

__global__ void __launch_bounds__(128) lstm_kernel(const float* __restrict__ gamma,
                                                   const float* __restrict__ beta,
                                                   float* __restrict__ out) {
    extern __shared__ float sm[];
    float* w_s = sm;                        // [1024][32]
    float* a_s = sm + H * 32;               // [64][AS_STRIDE]  h chunk, [b][k]
    float* mu_s = a_s + 64 * AS_STRIDE;     // [64]
    float* rs_s = mu_s + 64;                // [64]  (E[c^2])

    const int tid = threadIdx.x;
    const int cta = blockIdx.x;
    const int tx = tid & 7;                 // unit within CTA (4 permuted cols)
    const int ty = tid >> 3;                // batch group of 4
    const int col0 = cta * 32;
    const int unit = cta * 8 + tx;

    // load resident W slice
    for (int i = tid; i < H * 8; i += 128) {
        int k = i >> 3, n4 = i & 7;
        *(float4*)&w_s[k * 32 + n4 * 4] = *(const float4*)&g_Whp[(size_t)k * G + col0 + n4 * 4];
    }
    // zero h for my units
    for (int i = tid; i < B * 8; i += 128)
        g_h[(i >> 3) * H + cta * 8 + (i & 7)] = 0.f;

    const float gm = gamma[unit], bt = beta[unit];
    float c_reg[4] = {0.f, 0.f, 0.f, 0.f};

    __shared__ unsigned s_base;
    if (tid == 0) s_base = atomicAdd(&g_release, 0u);
    __syncthreads();
    unsigned gen = s_base;
    gridbar(++gen);                          // h zeros visible everywhere

    for (int t = 0; t < T; t++) {
        // prefetch xg_t tile (DRAM; independent of h, overlaps with GEMM)
        float4 xg4[4];
#pragma unroll
        for (int r = 0; r < 4; r++)
            xg4[r] = *(const float4*)&g_xg[(size_t)((ty * 4 + r) * T + t) * G + col0 + tx * 4];

        float4 acc[4];
#pragma unroll
        for (int r = 0; r < 4; r++) { acc[r].x = acc[r].y = acc[r].z = acc[r].w = 0.f; }

        // ---- acc[64x32] = h[64x1024] @ w_s[1024x32], in K-chunks of 128 ----
        for (int kc = 0; kc < H; kc += KC) {
            for (int i = tid; i < 64 * (KC / 4); i += 128) {
                int b = i >> 5, k4 = i & 31;
                *(float4*)&a_s[b * AS_STRIDE + k4 * 4] = *(const float4*)&g_h[b * H + kc + k4 * 4];
            }
            __syncthreads();
#pragma unroll 4
            for (int k4 = 0; k4 < KC / 4; k4++) {
                float4 a0 = *(const float4*)&a_s[(ty * 4 + 0) * AS_STRIDE + k4 * 4];
                float4 a1 = *(const float4*)&a_s[(ty * 4 + 1) * AS_STRIDE + k4 * 4];
                float4 a2 = *(const float4*)&a_s[(ty * 4 + 2) * AS_STRIDE + k4 * 4];
                float4 a3 = *(const float4*)&a_s[(ty * 4 + 3) * AS_STRIDE + k4 * 4];
#pragma unroll
                for (int kk = 0; kk < 4; kk++) {
                    float4 w = *(const float4*)&w_s[(kc + k4 * 4 + kk) * 32 + tx * 4];
                    float s0 = ((const float*)&a0)[kk];
                    float s1 = ((const float*)&a1)[kk];
                    float s2 = ((const float*)&a2)[kk];
                    float s3 = ((const float*)&a3)[kk];
                    FMA4(acc[0], s0, w); FMA4(acc[1], s1, w);
                    FMA4(acc[2], s2, w); FMA4(acc[3], s3, w);
                }
            }
            __syncthreads();
        }

        // ---- LSTM cell (permuted layout: .x=i, .y=f, .z=o, .w=g) ----
        float cp[4], og[4];
#pragma unroll
        for (int r = 0; r < 4; r++) {
            float ig = 1.f / (1.f + expf(-(acc[r].x + xg4[r].x)));
            float fg = 1.f / (1.f + expf(-(acc[r].y + xg4[r].y)));
            og[r]    = 1.f / (1.f + expf(-(acc[r].z + xg4[r].z)));
            float gg = tanhf(acc[r].w + xg4[r].w);
            cp[r] = fg * c_reg[r] + ig * gg;
        }

        // ---- LN partials: reduce over this CTA's 8 units per batch ----
#pragma unroll
        for (int r = 0; r < 4; r++) {
            float s = cp[r], s2 = cp[r] * cp[r];
#pragma unroll
            for (int m = 1; m < 8; m <<= 1) {
                s  += __shfl_xor_sync(0xffffffffu, s,  m);
                s2 += __shfl_xor_sync(0xffffffffu, s2, m);
            }
            if (tx == 0) {
                g_part[0][ty * 4 + r][cta] = s;
                g_part[1][ty * 4 + r][cta] = s2;
            }
        }
        gridbar(++gen);

        // ---- mean / E[c^2] per batch (deterministic fixed-order sum) ----
        {
            int b = tid & 63, hv = tid >> 6;
            float v = 0.f;
#pragma unroll 8
            for (int j = 0; j < NCTA; j++) v += g_part[hv][b][j];
            if (hv == 0) mu_s[b] = v * (1.f / H);
            else         rs_s[b] = v * (1.f / H);
        }
        __syncthreads();

        // ---- normalize c, compute h, write out ----
#pragma unroll
        for (int r = 0; r < 4; r++) {
            int b = ty * 4 + r;
            float mu = mu_s[b];
            float var = rs_s[b] - mu * mu;
            float cn = (cp[r] - mu) * rsqrtf(var + LN_EPS) * gm + bt;
            float hv2 = og[r] * tanhf(cn);
            c_reg[r] = cn;
            g_h[b * H + unit] = hv2;
            out[(size_t)(b * T + t) * H + unit] = hv2;
            if (t == T - 1) {
                out[(size_t)M1 * H + b * H + unit] = hv2;                 // h_f
                out[(size_t)M1 * H + (size_t)B * H + b * H + unit] = cn;  // c_f
            }
        }
        gridbar(++gen);
    }
}

// ---------------- launch ----------------
extern "C" void kernel_launch(void* const* d_in, const int* in_sizes, int n_in,
                              void* d_out, int out_size) {
    const int*   src = (const int*)d_in[0];
    const float* tab = (const float*)d_in[1];
    const float* Wi  = (const float*)d_in[2];
    const float* bi  = (const float*)d_in[3];
    const float* Wh  = (const float*)d_in[4];
    const float* bh  = (const float*)d_in[5];
    const float* gamma = (const float*)d_in[6];
    const float* beta  = (const float*)d_in[7];
    float* out = (float*)d_out;

    static bool attr_done = false;
    cudaFuncSetAttribute(lstm_kernel, cudaFuncAttributeMaxDynamicSharedMemorySize,
                         LSTM_SMEM_BYTES);
    (void)attr_done;

    prep_kernel<<<2048, 256>>>(Wi, bi, Wh, bh);
    embed_kernel<<<2048, 256>>>(src, tab);
    dim3 gg(G / 64, M1 / 128);
    xg_gemm<<<gg, 256>>>();
    lstm_kernel<<<NCTA, 128, LSTM_SMEM_BYTES>>>(gamma, beta, out);
}

// round 4
// speedup vs baseline: 1.8099x; 1.8099x over previous
#include <cuda_runtime.h>
#include <cuda_bf16.h>
#include <cstddef>
#include <cstdint>

#define VOCAB 32000
#define E 512
#define H 1024
#define G 4096            // 4*H
#define B 64
#define T 512
#define M1 (B*T)          // 32768
#define NCTA 128
#define LN_EPS 1e-5f

// ---------------- static device scratch (no cudaMalloc allowed) ----------------
__device__ float g_emb[(size_t)M1 * E];          // 64 MB   gathered embeddings
__device__ float g_xg[(size_t)M1 * G];           // 512 MB  xg = emb@W_i + (b_i+b_h), permuted cols
__device__ float g_Wip[(size_t)E * G];           // 8 MB    permuted W_i
__device__ __nv_bfloat16 g_Wbf[2][(size_t)G * H];// 16 MB   W_h^T permuted, [n][k], hi/lo split
__device__ float g_bp[G];                        // fused permuted bias
__device__ __nv_bfloat16 g_hbf[2][B * H];        // h state, bf16 hi/lo split
__device__ float g_part[2][B][NCTA];             // LN partials (sum, sumsq)
__device__ unsigned g_arrive;                    // grid-barrier arrivals (monotonic)
__device__ unsigned g_release;                   // grid-barrier release generation (monotonic)

// ---------------- prep: permute weights, fuse biases, split W_h to bf16 hi/lo ----------------
// permuted col p = 4*j + gate  <-  original col = gate*H + j   (gate order i,f,o,g)
__global__ void prep_kernel(const float* __restrict__ Wi, const float* __restrict__ bi,
                            const float* __restrict__ Wh, const float* __restrict__ bh) {
    int stride = gridDim.x * blockDim.x;
    for (int i = blockIdx.x * blockDim.x + threadIdx.x; i < H * G; i += stride) {
        int k = i >> 12;          // row
        int p = i & 4095;         // permuted col
        int j = p >> 2;
        int gi = p & 3;
        int oc = gi * H + j;      // original col
        float w = Wh[(size_t)k * G + oc];
        __nv_bfloat16 hi = __float2bfloat16(w);
        __nv_bfloat16 lo = __float2bfloat16(w - __bfloat162float(hi));
        g_Wbf[0][(size_t)p * H + k] = hi;   // [n][k] layout for ldmatrix B
        g_Wbf[1][(size_t)p * H + k] = lo;
        if (k < E) g_Wip[(size_t)k * G + p] = Wi[(size_t)k * G + oc];
        if (k == 0) g_bp[p] = bi[oc] + bh[oc];
    }
}

// ---------------- embedding gather (padding_idx = 0) ----------------
__global__ void embed_kernel(const int* __restrict__ src, const float* __restrict__ tab) {
    int total = M1 * (E / 4);
    int stride = gridDim.x * blockDim.x;
    for (int i = blockIdx.x * blockDim.x + threadIdx.x; i < total; i += stride) {
        int m = i >> 7;
        int e4 = i & 127;
        int row = src[m];
        float4 v;
        if (row == 0) { v.x = v.y = v.z = v.w = 0.f; }
        else v = *(const float4*)&tab[(size_t)row * E + e4 * 4];
        *(float4*)&g_emb[(size_t)m * E + e4 * 4] = v;
    }
}

// ---------------- phase-1 GEMM: xg = emb @ Wip + bp (fp32) ----------------
#define FMA4(ac, s, bv) { (ac).x += (s)*(bv).x; (ac).y += (s)*(bv).y; (ac).z += (s)*(bv).z; (ac).w += (s)*(bv).w; }

__global__ void __launch_bounds__(256) xg_gemm() {
    __shared__ float a_s[16][132];
    __shared__ float b_s[16][64];
    int tid = threadIdx.x;
    int n0 = blockIdx.x * 64;
    int m0 = blockIdx.y * 128;
    int tx = tid & 15;
    int ty = tid >> 4;
    float4 acc[8];
#pragma unroll
    for (int r = 0; r < 8; r++) { acc[r].x = acc[r].y = acc[r].z = acc[r].w = 0.f; }

    int lk = tid & 3, lm = tid >> 2;
    int bk = tid >> 4, bn = tid & 15;

    for (int kt = 0; kt < E; kt += 16) {
#pragma unroll
        for (int h2 = 0; h2 < 2; h2++) {
            int m = lm + h2 * 64;
            float4 v = *(const float4*)&g_emb[(size_t)(m0 + m) * E + kt + lk * 4];
            a_s[lk * 4 + 0][m] = v.x;
            a_s[lk * 4 + 1][m] = v.y;
            a_s[lk * 4 + 2][m] = v.z;
            a_s[lk * 4 + 3][m] = v.w;
        }
        *(float4*)&b_s[bk][bn * 4] = *(const float4*)&g_Wip[(size_t)(kt + bk) * G + n0 + bn * 4];
        __syncthreads();
#pragma unroll
        for (int k = 0; k < 16; k++) {
            float4 a0 = *(const float4*)&a_s[k][ty * 8];
            float4 a1 = *(const float4*)&a_s[k][ty * 8 + 4];
            float4 bv = *(const float4*)&b_s[k][tx * 4];
            FMA4(acc[0], a0.x, bv); FMA4(acc[1], a0.y, bv);
            FMA4(acc[2], a0.z, bv); FMA4(acc[3], a0.w, bv);
            FMA4(acc[4], a1.x, bv); FMA4(acc[5], a1.y, bv);
            FMA4(acc[6], a1.z, bv); FMA4(acc[7], a1.w, bv);
        }
        __syncthreads();
    }
    float4 bias = *(const float4*)&g_bp[n0 + tx * 4];
#pragma unroll
    for (int r = 0; r < 8; r++) {
        float4 o;
        o.x = acc[r].x + bias.x; o.y = acc[r].y + bias.y;
        o.z = acc[r].z + bias.z; o.w = acc[r].w + bias.w;
        *(float4*)&g_xg[(size_t)(m0 + ty * 8 + r) * G + n0 + tx * 4] = o;
    }
}

// ---------------- grid barrier (monotonic generation; graph-replay-safe) ----------------
__device__ __forceinline__ void gridbar(unsigned target) {
    __syncthreads();
    if (threadIdx.x == 0) {
        __threadfence();
        unsigned prev = atomicAdd(&g_arrive, 1u);
        if (prev + 1u == target * NCTA) {
            atomicExch(&g_release, target);
        } else {
            while (*(volatile unsigned*)&g_release < target) { __nanosleep(40); }
        }
        __threadfence();
    }
    __syncthreads();
}

// ---------------- tensor-core helpers ----------------
__device__ __forceinline__ uint32_t s2u(const void* p) {
    return (uint32_t)__cvta_generic_to_shared(p);
}
__device__ __forceinline__ void ldmx4(uint32_t& r0, uint32_t& r1, uint32_t& r2, uint32_t& r3,
                                      uint32_t addr) {
    asm volatile("ldmatrix.sync.aligned.m8n8.x4.shared.b16 {%0,%1,%2,%3}, [%4];"
                 : "=r"(r0), "=r"(r1), "=r"(r2), "=r"(r3) : "r"(addr));
}
__device__ __forceinline__ void ldmx2(uint32_t& r0, uint32_t& r1, uint32_t addr) {
    asm volatile("ldmatrix.sync.aligned.m8n8.x2.shared.b16 {%0,%1}, [%2];"
                 : "=r"(r0), "=r"(r1) : "r"(addr));
}
__device__ __forceinline__ void mma16816(float* d, const uint32_t* a, const uint32_t* b) {
    asm volatile("mma.sync.aligned.m16n8k16.row.col.f32.bf16.bf16.f32 "
                 "{%0,%1,%2,%3},{%4,%5,%6,%7},{%8,%9},{%0,%1,%2,%3};"
                 : "+f"(d[0]), "+f"(d[1]), "+f"(d[2]), "+f"(d[3])
                 : "r"(a[0]), "r"(a[1]), "r"(a[2]), "r"(a[3]), "r"(b[0]), "r"(b[1]));
}

// ---------------- persistent recurrent kernel (tensor core, split-bf16) ----------------
// 128 CTAs x 128 threads. CTA owns permuted cols [32*cta, 32*cta+32) = units [8*cta, 8*cta+8).
// W_h^T slice [32 n][1024 k] resident in SMEM as bf16 hi/lo (padded stride, conflict-free ldmatrix).
// Warp w handles batch rows [16w, 16w+16), all 32 cols. K streamed in 8 chunks of 128.
#define KC 128
#define BSTR 2064                        // B row stride bytes (1024*2 + 16)
#define ASTR 272                         // A row stride bytes (128*2 + 16)
#define OFF_BH 0
#define OFF_BL (32*BSTR)                 // 66048
#define OFF_AH (2*32*BSTR)               // 132096
#define OFF_AL (OFF_AH + 64*ASTR)        // 149504
#define OFF_CP (OFF_AL + 64*ASTR)        // 166912  cp_s: [8][65] f32
#define OFF_OG (OFF_CP + 520*4)          // og_s
#define OFF_CS (OFF_OG + 520*4)          // c_s (carried cell state)
#define OFF_MU (OFF_CS + 520*4)          // mu_s [64]
#define OFF_RS (OFF_MU + 256)            // rs_s [64]
#define LSTM_SMEM_BYTES (OFF_RS + 256)   // 173664

__global__ void __launch_bounds__(128) lstm_kernel(const float* __restrict__ gamma,
                                                   const float* __restrict__ beta,
                                                   float* __restrict__ out) {
    extern __shared__ char sm[];
    float* cp_s = (float*)(sm + OFF_CP);
    float* og_s = (float*)(sm + OFF_OG);
    float* c_s  = (float*)(sm + OFF_CS);
    float* mu_s = (float*)(sm + OFF_MU);
    float* rs_s = (float*)(sm + OFF_RS);

    const int tid = threadIdx.x;
    const int cta = blockIdx.x;
    const int w   = tid >> 5;             // warp 0..3 -> batch rows [16w,16w+16)
    const int l   = tid & 31;             // lane
    const int col0 = cta * 32;

    const uint32_t sbase = s2u(sm);

    // ---- load resident W^T slice (bf16 hi/lo) into padded smem ----
    for (int idx = tid; idx < 2 * 32 * 128; idx += 128) {   // 8192 uint4
        int half = idx >> 12;
        int rem  = idx & 4095;
        int n    = rem >> 7;
        int kq   = rem & 127;             // uint4 = 8 bf16
        uint4 v = *(const uint4*)&g_Wbf[half][(size_t)(col0 + n) * H + kq * 8];
        *(uint4*)(sm + (half ? OFF_BL : OFF_BH) + n * BSTR + kq * 16) = v;
    }
    // ---- zero h (bf16 hi/lo) for my units, zero carried c ----
    for (int i = tid; i < B * 8; i += 128) {
        int b = i >> 3, u = i & 7;
        g_hbf[0][b * H + cta * 8 + u] = __float2bfloat16(0.f);
        g_hbf[1][b * H + cta * 8 + u] = __float2bfloat16(0.f);
    }
    for (int i = tid; i < 520; i += 128) c_s[i] = 0.f;

    __shared__ unsigned s_base;
    if (tid == 0) s_base = *(volatile unsigned*)&g_release;
    __syncthreads();
    unsigned gen = s_base;
    gridbar(++gen);                       // h zeros visible everywhere

    // per-lane epilogue mapping
    const int lq = l >> 2;                // 0..7
    const int ls = (l & 3) >> 1;          // unit parity within n-tile
    const int bmy = 16 * w + lq + 8 * (l & 1);   // my batch
    const bool evenRole = ((l & 1) == 0);

    // ldmatrix A address pieces (per lane)
    const int a_row  = 16 * w + (l & 7) + 8 * ((l >> 3) & 1);
    const int a_k16  = (l >> 4) * 16;     // byte offset for k+8 tiles
    const int b_lane = l & 15;
    const int b_rowi = b_lane & 7;
    const int b_k16  = (b_lane >> 3) * 16;

    for (int t = 0; t < T; t++) {
        // prefetch xg for my 4 cells (batch bmy, units u = 2*nt + ls)
        float4 xg4[4];
#pragma unroll
        for (int nt = 0; nt < 4; nt++) {
            int u = 2 * nt + ls;
            xg4[nt] = *(const float4*)&g_xg[(size_t)(bmy * T + t) * G + col0 + u * 4];
        }

        float acc[4][4];
#pragma unroll
        for (int nt = 0; nt < 4; nt++)
#pragma unroll
            for (int r = 0; r < 4; r++) acc[nt][r] = 0.f;

        // ---- GEMM: acc = h[64x1024] @ W^T, split-bf16 (3 MMAs) ----
        for (int kc = 0; kc < H; kc += KC) {
            // stage h chunk (hi+lo) into padded smem
#pragma unroll
            for (int j = 0; j < 16; j++) {
                int idx = tid + j * 128;          // 0..2047
                int half = idx >> 10;
                int rem  = idx & 1023;
                int b    = rem >> 4;
                int kq   = rem & 15;
                uint4 v = *(const uint4*)&g_hbf[half][b * H + kc + kq * 8];
                *(uint4*)(sm + (half ? OFF_AL : OFF_AH) + b * ASTR + kq * 16) = v;
            }
            __syncthreads();
#pragma unroll
            for (int kt = 0; kt < 8; kt++) {
                uint32_t ah[4], al[4];
                uint32_t a_off = a_row * ASTR + kt * 32 + a_k16;
                ldmx4(ah[0], ah[1], ah[2], ah[3], sbase + OFF_AH + a_off);
                ldmx4(al[0], al[1], al[2], al[3], sbase + OFF_AL + a_off);
#pragma unroll
                for (int nt = 0; nt < 4; nt++) {
                    uint32_t bh[2], blr[2];
                    uint32_t b_off = (nt * 8 + b_rowi) * BSTR + (kc + kt * 16) * 2 + b_k16;
                    ldmx2(bh[0], bh[1], sbase + OFF_BH + b_off);
                    ldmx2(blr[0], blr[1], sbase + OFF_BL + b_off);
                    mma16816(acc[nt], ah, bh);
                    mma16816(acc[nt], ah, blr);
                    mma16816(acc[nt], al, bh);
                }
            }
            __syncthreads();
        }

        // ---- LSTM cell: shfl-pair to assemble 4 gates per (batch, unit) ----
#pragma unroll
        for (int nt = 0; nt < 4; nt++) {
            float t0 = __shfl_xor_sync(0xffffffffu, acc[nt][0], 1);
            float t1 = __shfl_xor_sync(0xffffffffu, acc[nt][1], 1);
            float t2 = __shfl_xor_sync(0xffffffffu, acc[nt][2], 1);
            float t3 = __shfl_xor_sync(0xffffffffu, acc[nt][3], 1);
            float iv, fv, ov, gv;
            if (evenRole) { iv = acc[nt][0]; fv = acc[nt][1]; ov = t0; gv = t1; }
            else          { iv = t2;         fv = t3;         ov = acc[nt][2]; gv = acc[nt][3]; }
            int u = 2 * nt + ls;
            float ig = 1.f / (1.f + expf(-(iv + xg4[nt].x)));
            float fg = 1.f / (1.f + expf(-(fv + xg4[nt].y)));
            float og = 1.f / (1.f + expf(-(ov + xg4[nt].z)));
            float gg = tanhf(gv + xg4[nt].w);
            float cprev = c_s[u * 65 + bmy];
            float cp = fg * cprev + ig * gg;
            cp_s[u * 65 + bmy] = cp;
            og_s[u * 65 + bmy] = og;
        }
        __syncthreads();

        // ---- LN partials for this CTA's 8 units ----
        {
            int b = tid & 63, hv = tid >> 6;
            float v = 0.f;
#pragma unroll
            for (int u = 0; u < 8; u++) {
                float x = cp_s[u * 65 + b];
                v += hv ? x * x : x;
            }
            g_part[hv][b][cta] = v;
        }
        gridbar(++gen);

        // ---- mean / E[c^2] per batch (deterministic fixed-order sum) ----
        {
            int b = tid & 63, hv = tid >> 6;
            float v = 0.f;
#pragma unroll 8
            for (int j = 0; j < NCTA; j++) v += g_part[hv][b][j];
            if (hv == 0) mu_s[b] = v * (1.f / H);
            else         rs_s[b] = v * (1.f / H);
        }
        __syncthreads();

        // ---- normalize c, compute h, write out + bf16 hi/lo state ----
        {
            int tx = tid & 7;             // unit
            int ty = tid >> 3;            // 0..15
            int unit = cta * 8 + tx;
            float gm = gamma[unit], bt = beta[unit];
#pragma unroll
            for (int r = 0; r < 4; r++) {
                int b = ty * 4 + r;
                float mu = mu_s[b];
                float var = rs_s[b] - mu * mu;
                float cp = cp_s[tx * 65 + b];
                float cn = (cp - mu) * rsqrtf(var + LN_EPS) * gm + bt;
                float hv2 = og_s[tx * 65 + b] * tanhf(cn);
                c_s[tx * 65 + b] = cn;
                __nv_bfloat16 hh = __float2bfloat16(hv2);
                __nv_bfloat16 hl = __float2bfloat16(hv2 - __bfloat162float(hh));
                g_hbf[0][b * H + unit] = hh;
                g_hbf[1][b * H + unit] = hl;
                out[(size_t)(b * T + t) * H + unit] = hv2;
                if (t == T - 1) {
                    out[(size_t)M1 * H + b * H + unit] = hv2;                 // h_f
                    out[(size_t)M1 * H + (size_t)B * H + b * H + unit] = cn;  // c_f
                }
            }
        }
        gridbar(++gen);
    }
}

// ---------------- launch ----------------
extern "C" void kernel_launch(void* const* d_in, const int* in_sizes, int n_in,
                              void* d_out, int out_size) {
    const int*   src = (const int*)d_in[0];
    const float* tab = (const float*)d_in[1];
    const float* Wi  = (const float*)d_in[2];
    const float* bi  = (const float*)d_in[3];
    const float* Wh  = (const float*)d_in[4];
    const float* bh  = (const float*)d_in[5];
    const float* gamma = (const float*)d_in[6];
    const float* beta  = (const float*)d_in[7];
    float* out = (float*)d_out;

    cudaFuncSetAttribute(lstm_kernel, cudaFuncAttributeMaxDynamicSharedMemorySize,
                         LSTM_SMEM_BYTES);

    prep_kernel<<<2048, 256>>>(Wi, bi, Wh, bh);
    embed_kernel<<<2048, 256>>>(src, tab);
    dim3 gg(G / 64, M1 / 128);
    xg_gemm<<<gg, 256>>>();
    lstm_kernel<<<NCTA, 128, LSTM_SMEM_BYTES>>>(gamma, beta, out);
}